// round 10
// baseline (speedup 1.0000x reference)
#include <cuda_runtime.h>
#include <cuda_fp16.h>
#include <cstdint>
#include <math.h>

#define HDIM   512
#define BDIM   512
#define GDIM   2048
#define NSTEPS 30
#define BH     (BDIM * HDIM)
#define BH2    (BDIM * 256)          // half2 per [512,512] plane
#define WPL2   (2048 * 256)          // half2 per [2048,512] weight plane
#define WSZF   ((size_t)GDIM * HDIM) // fp32 weight plane elems

__device__ __align__(1024) __half2 g_w16ih[60 * WPL2];   // 125.8 MB
__device__ __align__(1024) __half2 g_w16hh[60 * WPL2];   // 125.8 MB
__device__ __align__(1024) __half2 g_x16[NSTEPS * BH2];  // 15.7 MB
__device__ __align__(1024) __half2 g_h16[4 * BH2];       // [parity][layer], 2 MB
__device__ __align__(1024) float   g_c[2 * BH];          // 2 MB

// ---------------- helpers ----------------
__device__ __forceinline__ uint32_t smem_u32(const void* p) {
    uint32_t a;
    asm("{ .reg .u64 t; cvta.to.shared.u64 t, %1; cvt.u32.u64 %0, t; }" : "=r"(a) : "l"(p));
    return a;
}
#define CP_ASYNC16(dst_u32, src_ptr) \
    asm volatile("cp.async.cg.shared.global [%0], [%1], 16;" \
                 :: "r"(dst_u32), "l"(src_ptr) : "memory")
#define CP_COMMIT() asm volatile("cp.async.commit_group;" ::: "memory")
#define CP_WAIT1()  asm volatile("cp.async.wait_group 1;" ::: "memory")

__device__ __forceinline__ void mma_f16(float* d,
                                        uint32_t a0, uint32_t a1, uint32_t a2, uint32_t a3,
                                        uint32_t b0, uint32_t b1) {
    asm volatile(
        "mma.sync.aligned.m16n8k16.row.col.f32.f16.f16.f32 "
        "{%0,%1,%2,%3}, {%4,%5,%6,%7}, {%8,%9}, {%0,%1,%2,%3};"
        : "+f"(d[0]), "+f"(d[1]), "+f"(d[2]), "+f"(d[3])
        : "r"(a0), "r"(a1), "r"(a2), "r"(a3), "r"(b0), "r"(b1));
}
__device__ __forceinline__ float fast_sigmoid(float x) {
    return __fdividef(1.0f, 1.0f + __expf(-x));
}
__device__ __forceinline__ float fast_tanh(float x) {
    return 1.0f - __fdividef(2.0f, __expf(2.0f * x) + 1.0f);
}
__device__ __forceinline__ uint32_t pk(float a, float b) {
    __half2 h = __floats2half2_rn(a, b);
    return *reinterpret_cast<uint32_t*>(&h);
}

// ---------------- vectorized fp32 -> permuted fp16 chunk converter ----------------
__device__ __forceinline__ void convert_chunk(const float* __restrict__ src,
                                              __half2* __restrict__ dst, int c) {
    const int row = c >> 4, cb = c & 15;
    const float4* s4 = (const float4*)(src + ((size_t)row << 9) + (cb << 5));
    float f[32];
#pragma unroll
    for (int q = 0; q < 8; q++) {
        float4 v = s4[q];
        f[q * 4 + 0] = v.x; f[q * 4 + 1] = v.y; f[q * 4 + 2] = v.z; f[q * 4 + 3] = v.w;
    }
    uint32_t o[16];
#pragma unroll
    for (int p = 0; p < 16; p++) {
        int q = (p & 3) * 4 + (p >> 2);
        o[p] = pk(f[2 * q], f[2 * q + 1]);
    }
    uint4* d4 = (uint4*)(dst + ((size_t)row << 8) + (cb << 4));
#pragma unroll
    for (int v = 0; v < 4; v++)
        d4[v] = make_uint4(o[v * 4], o[v * 4 + 1], o[v * 4 + 2], o[v * 4 + 3]);
}

// ---------------- smem layout (bytes) ----------------
// stage: A 128x32 half = 8192 + W 128x32 half = 8192 -> 16384; 6 stages
#define NSTAGE    6
#define STAGE_B   16384
#define OFF_W     8192
#define SMC_OFF   (NSTAGE * STAGE_B)        // 98304: c tile [128][36] floats = 18432
#define BIAS_OFF  (SMC_OFF + 128 * 36 * 4)  // 116736
#define SMEM_BYTES (BIAS_OFF + 512)         // 117248
#define NKB 32
#define CPAD 36
#define NCONV 20                            // dedicated converter SMs
#define CHUNKS_PER_TENSOR 65536

struct Job {
    const __half2* A1; const __half2* A2;   // fp16 permuted [512][256]
    const __half2* W1; const __half2* W2;   // fp16 permuted [2048][256]
    const float* b1;   const float* b2;
    float* c; __half2* h16; float* y; float* h32;
};

__device__ __forceinline__ void issue_stage(uint32_t sb, int s, int it, const Job& j,
                                            int m0, int j0, int tid) {
    const __half2* Ap = (it < 16) ? j.A1 : j.A2;
    const __half2* Wp = (it < 16) ? j.W1 : j.W2;
    const int kk = (it & 15) << 4;
    const uint32_t as = sb + s * STAGE_B;
    const uint32_t ws = as + OFF_W;
#pragma unroll
    for (int t2 = 0; t2 < 2; t2++) {    // A: 128 rows x 4 chunks = 512 tasks, 2/thread
        int idx = tid + t2 * 256;
        int row = idx >> 2, u = idx & 3;
        CP_ASYNC16(as + (row << 6) + (u << 4),
                   Ap + (size_t)(m0 + row) * 256 + kk + u * 4);
    }
#pragma unroll
    for (int t2 = 0; t2 < 2; t2++) {    // W: 128 rows x 4 chunks = 512 tasks, 2/thread
        int idx = tid + t2 * 256;
        int r = idx >> 2, u = idx & 3;
        int grow = (r & 3) * 512 + j0 + (r >> 2);
        CP_ASYNC16(ws + (r << 6) + (u << 4),
                   Wp + (size_t)grow * 256 + kk + u * 4);
    }
}

__global__ __launch_bounds__(256, 1) void lstm_pair(
    Job jobA, Job jobB, int nJobCtas,
    const float* __restrict__ cIh, const float* __restrict__ cHh,
    __half2* __restrict__ dIh, __half2* __restrict__ dHh)
{
    const int cta = blockIdx.x;
    const int tid = threadIdx.x;

    // ---- converter CTAs: run on their own SMs (grid = nJob + NCONV <= 148) ----
    if (cta >= nJobCtas) {
        if (dIh == nullptr) return;
        const int w = cta - nJobCtas;
        for (int c = w * 256 + tid; c < 2 * CHUNKS_PER_TENSOR; c += NCONV * 256) {
            if (c < CHUNKS_PER_TENSOR) convert_chunk(cIh, dIh, c);
            else                       convert_chunk(cHh, dHh, c - CHUNKS_PER_TENSOR);
        }
        return;
    }

    extern __shared__ char smem[];
    const uint32_t sb = smem_u32(smem);
    const Job j = (cta < 64) ? jobA : jobB;
    const int tile = cta & 63;
    const int m0 = (tile >> 4) * 128;       // 4 m-blocks x 128 rows
    const int j0 = (tile & 15) * 32;        // 16 j-blocks x 32 cols

    const int lane = tid & 31;
    const int wid  = tid >> 5;
    const int wm = wid & 3;          // 4 m-groups x 32 rows
    const int wn = wid >> 2;         // 2 n-groups x 64 n_local
    const int r4 = lane >> 2;
    const int u  = lane & 3;

    float* smb = (float*)(smem + BIAS_OFF);
    if (tid < 128) {   // guard load-bearing: smb is 128 floats, bias plane is 2048
        int g = tid >> 5, jj = tid & 31;
        smb[tid] = j.b1[g * 512 + j0 + jj] + j.b2[g * 512 + j0 + jj];
    }

    float acc[2][8][4];
#pragma unroll
    for (int mt = 0; mt < 2; mt++)
#pragma unroll
        for (int nt = 0; nt < 8; nt++)
#pragma unroll
            for (int e = 0; e < 4; e++) acc[mt][nt][e] = 0.f;

    // prologue: c prefetch (group 0) + stages 0,1 ; then stages 2,3
    {
        const uint32_t smc_a = sb + SMC_OFF;
#pragma unroll
        for (int v = 0; v < 4; v++) {       // 128 rows x 8 chunks = 1024 tasks
            int idx = tid + v * 256;
            int r = idx >> 3, ch = idx & 7;
            CP_ASYNC16(smc_a + r * (CPAD * 4) + (ch << 4),
                       j.c + (size_t)(m0 + r) * HDIM + j0 + ch * 4);
        }
    }
    issue_stage(sb, 0, 0, j, m0, j0, tid);
    issue_stage(sb, 1, 1, j, m0, j0, tid); CP_COMMIT();
    issue_stage(sb, 2, 2, j, m0, j0, tid);
    issue_stage(sb, 3, 3, j, m0, j0, tid); CP_COMMIT();

    const int aoff = ((wm * 32 + r4) << 6) + (u << 4);
    const int boff = ((wn * 64 + r4) << 6) + (u << 4) + OFF_W;

    int s = 0;
    for (int itp = 0; itp < NKB; itp += 2) {
        CP_WAIT1();
        __syncthreads();
        if (itp + 4 < NKB) {
            int s4 = s + 4; if (s4 >= NSTAGE) s4 -= NSTAGE;
            int s5 = s4 + 1; if (s5 >= NSTAGE) s5 -= NSTAGE;
            issue_stage(sb, s4, itp + 4, j, m0, j0, tid);
            issue_stage(sb, s5, itp + 5, j, m0, j0, tid);
        }
        CP_COMMIT();

#pragma unroll
        for (int h = 0; h < 2; h++) {
            const char* st = smem + (s + h) * STAGE_B;
            uint4 a0lo = *(const uint4*)(st + aoff);
            uint4 a0hi = *(const uint4*)(st + aoff + 512);
            uint4 a1lo = *(const uint4*)(st + aoff + 1024);
            uint4 a1hi = *(const uint4*)(st + aoff + 1536);
#pragma unroll
            for (int nt = 0; nt < 8; nt++) {
                uint4 bb = *(const uint4*)(st + boff + (nt << 9));
                mma_f16(acc[0][nt], a0lo.x, a0hi.x, a0lo.y, a0hi.y, bb.x, bb.y);
                mma_f16(acc[0][nt], a0lo.z, a0hi.z, a0lo.w, a0hi.w, bb.z, bb.w);
                mma_f16(acc[1][nt], a1lo.x, a1hi.x, a1lo.y, a1hi.y, bb.x, bb.y);
                mma_f16(acc[1][nt], a1lo.z, a1hi.z, a1lo.w, a1hi.w, bb.z, bb.w);
            }
        }
        s += 2; if (s == NSTAGE) s = 0;
    }

    // ---------------- fused LSTM cell epilogue ----------------
    __syncthreads();
    float* smc = (float*)(smem + SMC_OFF);
    float* smh = (float*)smem;              // [128][36] overlays stage region (18432 B)

    const bool evn = !(u & 1);
#pragma unroll
    for (int mt = 0; mt < 2; mt++) {
        const int row = wm * 32 + mt * 16 + r4 + (evn ? 0 : 8);
#pragma unroll
        for (int nt = 0; nt < 8; nt++) {
            float x0 = __shfl_xor_sync(0xFFFFFFFFu, acc[mt][nt][0], 1);
            float x1 = __shfl_xor_sync(0xFFFFFFFFu, acc[mt][nt][1], 1);
            float x2 = __shfl_xor_sync(0xFFFFFFFFu, acc[mt][nt][2], 1);
            float x3 = __shfl_xor_sync(0xFFFFFFFFu, acc[mt][nt][3], 1);
            int jj = wn * 16 + nt * 2 + (u >> 1);
            float vi = (evn ? acc[mt][nt][0] : x2) + smb[jj];
            float vf = (evn ? acc[mt][nt][1] : x3) + smb[32 + jj];
            float vg = (evn ? x0 : acc[mt][nt][2]) + smb[64 + jj];
            float vo = (evn ? x1 : acc[mt][nt][3]) + smb[96 + jj];
            float ii = fast_sigmoid(vi);
            float ff = fast_sigmoid(vf);
            float gg = fast_tanh(vg);
            float oo = fast_sigmoid(vo);
            float cn = ff * smc[row * CPAD + jj] + ii * gg;
            float hn = oo * fast_tanh(cn);
            smc[row * CPAD + jj] = cn;
            smh[row * CPAD + jj] = hn;
        }
    }
    __syncthreads();

    for (int i = tid; i < 128 * 32; i += 256) {
        int r = i >> 5, jj = i & 31;
        size_t g = (size_t)(m0 + r) * HDIM + j0 + jj;
        j.c[g] = smc[r * CPAD + jj];
        float hv = smh[r * CPAD + jj];
        if (j.y)   j.y[g]   = hv;
        if (j.h32) j.h32[g] = hv;
    }
    for (int i = tid; i < 128 * 16; i += 256) {
        int r = i >> 4, q = i & 15;
        int p = (q & 3) * 4 + (q >> 2);
        __half2 hv = __floats2half2_rn(smh[r * CPAD + 2 * q], smh[r * CPAD + 2 * q + 1]);
        j.h16[(size_t)(m0 + r) * 256 + (j0 >> 1) + p] = hv;
    }
}

// standalone chunk conversion (upfront: x + step-0 weights)
__global__ __launch_bounds__(256) void conv_chunks(const float* __restrict__ src,
                                                   __half2* __restrict__ dst, int nChunks) {
    int c = blockIdx.x * 256 + threadIdx.x;
    if (c < nChunks) convert_chunk(src, dst, c);
}

__global__ void zero_state() {
    int i = blockIdx.x * 256 + threadIdx.x;
    if (i < 2 * BH2) g_h16[2 * BH2 + i] = __floats2half2_rn(0.f, 0.f);
    if (i < 2 * BH)  g_c[i] = 0.f;
}

// ---------------- host ----------------
extern "C" void kernel_launch(void* const* d_in, const int* in_sizes, int n_in,
                              void* d_out, int out_size)
{
    const float* x    = (const float*)d_in[0];
    const float* W_ih = (const float*)d_in[1];
    const float* W_hh = (const float*)d_in[2];
    const float* b_ih = (const float*)d_in[3];
    const float* b_hh = (const float*)d_in[4];
    float* out = (float*)d_out;

    __half2 *w16ih, *w16hh, *x16, *h16;
    float* cbuf;
    cudaGetSymbolAddress((void**)&w16ih, g_w16ih);
    cudaGetSymbolAddress((void**)&w16hh, g_w16hh);
    cudaGetSymbolAddress((void**)&x16,   g_x16);
    cudaGetSymbolAddress((void**)&h16,   g_h16);
    cudaGetSymbolAddress((void**)&cbuf,  g_c);

    cudaFuncSetAttribute(lstm_pair, cudaFuncAttributeMaxDynamicSharedMemorySize, SMEM_BYTES);

    // upfront: x, step-0 weights, state zero
    conv_chunks<<<(NSTEPS * 512 * 16 + 255) / 256, 256>>>(x, x16, NSTEPS * 512 * 16);
    conv_chunks<<<(CHUNKS_PER_TENSOR + 255) / 256, 256>>>(W_ih, w16ih, CHUNKS_PER_TENSOR);
    conv_chunks<<<(CHUNKS_PER_TENSOR + 255) / 256, 256>>>(W_hh, w16hh, CHUNKS_PER_TENSOR);
    zero_state<<<(2 * BH + 255) / 256, 256>>>();

    auto mkL0 = [&](int t) -> Job {
        int xt = (t < NSTEPS - 1) ? t : NSTEPS - 2;    // source bug: step 29 reuses x[28]
        int wp = t & 1, rp = wp ^ 1;
        Job jb;
        jb.A1 = x16 + (size_t)xt * BH2;
        jb.A2 = h16 + (size_t)(rp * 2 + 0) * BH2;
        jb.W1 = w16ih + (size_t)(t * 2 + 0) * WPL2;
        jb.W2 = w16hh + (size_t)(t * 2 + 0) * WPL2;
        jb.b1 = b_ih + (size_t)(t * 2 + 0) * GDIM;
        jb.b2 = b_hh + (size_t)(t * 2 + 0) * GDIM;
        jb.c  = cbuf;
        jb.h16 = h16 + (size_t)(wp * 2 + 0) * BH2;
        jb.y = nullptr;
        jb.h32 = (t == NSTEPS - 1) ? (out + (size_t)NSTEPS * BH) : nullptr;
        return jb;
    };
    auto mkL1 = [&](int t) -> Job {
        int wp = t & 1, rp = wp ^ 1;
        Job jb;
        jb.A1 = h16 + (size_t)(wp * 2 + 0) * BH2;
        jb.A2 = h16 + (size_t)(rp * 2 + 1) * BH2;
        jb.W1 = w16ih + (size_t)(t * 2 + 1) * WPL2;
        jb.W2 = w16hh + (size_t)(t * 2 + 1) * WPL2;
        jb.b1 = b_ih + (size_t)(t * 2 + 1) * GDIM;
        jb.b2 = b_hh + (size_t)(t * 2 + 1) * GDIM;
        jb.c  = cbuf + BH;
        jb.h16 = h16 + (size_t)(wp * 2 + 1) * BH2;
        jb.y = out + (size_t)t * BH;
        jb.h32 = (t == NSTEPS - 1) ? (out + (size_t)(NSTEPS + 1) * BH) : nullptr;
        return jb;
    };

    // launch i: L0(i) [+ L1(i-1)]; converter CTAs (dedicated SMs) prepare step i+1
    for (int i = 0; i <= NSTEPS; i++) {
        Job a, b;
        int nJob;
        if (i == 0)            { a = mkL0(0); b = a; nJob = 64; }
        else if (i == NSTEPS)  { a = mkL1(NSTEPS - 1); b = a; nJob = 64; }
        else                   { a = mkL0(i); b = mkL1(i - 1); nJob = 128; }

        int sN = i + 1;
        const float* cIh = nullptr; const float* cHh = nullptr;
        __half2* dIh = nullptr; __half2* dHh = nullptr;
        int nconv = 0;
        if (sN < NSTEPS) {
            cIh = W_ih + (size_t)(sN * 2) * WSZF;
            cHh = W_hh + (size_t)(sN * 2) * WSZF;
            dIh = w16ih + (size_t)(sN * 2) * WPL2;
            dHh = w16hh + (size_t)(sN * 2) * WPL2;
            nconv = NCONV;
        }
        lstm_pair<<<nJob + nconv, 256, SMEM_BYTES>>>(a, b, nJob, cIh, cHh, dIh, dHh);
    }

    cudaMemcpyAsync(out + (size_t)(NSTEPS + 2) * BH, cbuf,
                    2 * BH * sizeof(float), cudaMemcpyDeviceToDevice);
}

// round 11
// speedup vs baseline: 1.5074x; 1.5074x over previous
#include <cuda_runtime.h>
#include <cuda_fp16.h>
#include <cstdint>
#include <math.h>

#define HDIM   512
#define BDIM   512
#define GDIM   2048
#define NSTEPS 30
#define BH     (BDIM * HDIM)
#define BH2    (BDIM * 256)          // half2 per [512,512] plane
#define WPL2   (2048 * 256)          // half2 per [2048,512] weight plane
#define WSZF   ((size_t)GDIM * HDIM) // fp32 weight plane elems

__device__ __align__(1024) __half2 g_w16ih[60 * WPL2];   // 125.8 MB
__device__ __align__(1024) __half2 g_w16hh[60 * WPL2];   // 125.8 MB
__device__ __align__(1024) __half2 g_x16[NSTEPS * BH2];  // 15.7 MB
__device__ __align__(1024) __half2 g_h16[4 * BH2];       // [parity][layer], 2 MB
__device__ unsigned g_count;    // barrier arrivals (returns to 0 every barrier)
__device__ unsigned g_epoch;    // barrier epoch (monotonic across replays)

// ---------------- helpers ----------------
__device__ __forceinline__ uint32_t smem_u32(const void* p) {
    uint32_t a;
    asm("{ .reg .u64 t; cvta.to.shared.u64 t, %1; cvt.u32.u64 %0, t; }" : "=r"(a) : "l"(p));
    return a;
}
#define CP_ASYNC16(dst_u32, src_ptr) \
    asm volatile("cp.async.cg.shared.global [%0], [%1], 16;" \
                 :: "r"(dst_u32), "l"(src_ptr) : "memory")
#define CP_COMMIT() asm volatile("cp.async.commit_group;" ::: "memory")
#define CP_WAIT1()  asm volatile("cp.async.wait_group 1;" ::: "memory")

__device__ __forceinline__ void mma_f16(float* d,
                                        uint32_t a0, uint32_t a1, uint32_t a2, uint32_t a3,
                                        uint32_t b0, uint32_t b1) {
    asm volatile(
        "mma.sync.aligned.m16n8k16.row.col.f32.f16.f16.f32 "
        "{%0,%1,%2,%3}, {%4,%5,%6,%7}, {%8,%9}, {%0,%1,%2,%3};"
        : "+f"(d[0]), "+f"(d[1]), "+f"(d[2]), "+f"(d[3])
        : "r"(a0), "r"(a1), "r"(a2), "r"(a3), "r"(b0), "r"(b1));
}
__device__ __forceinline__ float fast_sigmoid(float x) {
    return __fdividef(1.0f, 1.0f + __expf(-x));
}
__device__ __forceinline__ float fast_tanh(float x) {
    return 1.0f - __fdividef(2.0f, __expf(2.0f * x) + 1.0f);
}
__device__ __forceinline__ uint32_t pk(float a, float b) {
    __half2 h = __floats2half2_rn(a, b);
    return *reinterpret_cast<uint32_t*>(&h);
}

// ---------------- vectorized fp32 -> permuted fp16 chunk converter ----------------
__device__ __forceinline__ void convert_chunk(const float* __restrict__ src,
                                              __half2* __restrict__ dst, int c) {
    const int row = c >> 4, cb = c & 15;
    const float4* s4 = (const float4*)(src + ((size_t)row << 9) + (cb << 5));
    float f[32];
#pragma unroll
    for (int q = 0; q < 8; q++) {
        float4 v = s4[q];
        f[q * 4 + 0] = v.x; f[q * 4 + 1] = v.y; f[q * 4 + 2] = v.z; f[q * 4 + 3] = v.w;
    }
    uint32_t o[16];
#pragma unroll
    for (int p = 0; p < 16; p++) {
        int q = (p & 3) * 4 + (p >> 2);
        o[p] = pk(f[2 * q], f[2 * q + 1]);
    }
    uint4* d4 = (uint4*)(dst + ((size_t)row << 8) + (cb << 4));
#pragma unroll
    for (int v = 0; v < 4; v++)
        d4[v] = make_uint4(o[v * 4], o[v * 4 + 1], o[v * 4 + 2], o[v * 4 + 3]);
}

// ---------------- smem layout (bytes) ----------------
#define NSTAGE    6
#define STAGE_B   12288
#define OFF_W     4096
#define SMC_OFF   (NSTAGE * STAGE_B)        // 73728: c tile [64][36] floats
#define BIAS_OFF  (SMC_OFF + 64 * 36 * 4)   // 82944
#define SMEM_BYTES (BIAS_OFF + 512)         // 83456
#define NKB 32
#define CPAD 36
#define NJOB  256
#define NCONV 40
#define NCTAS (NJOB + NCONV)                // 296 = 2/SM x 148 SMs
#define CHUNKS_PER_TENSOR 65536

// ---------------- software grid barrier (all NCTAS co-resident) ----------------
__device__ __forceinline__ void grid_barrier() {
    __syncthreads();
    if (threadIdx.x == 0) {
        __threadfence();                                  // release: h16/y/w16 stores visible
        unsigned old = *(volatile unsigned*)&g_epoch;     // epoch can't advance until my arrival
        if (atomicAdd(&g_count, 1u) == NCTAS - 1) {
            atomicExch(&g_count, 0u);
            __threadfence();
            *(volatile unsigned*)&g_epoch = old + 1;
        } else {
            while (*(volatile unsigned*)&g_epoch == old) __nanosleep(64);
        }
        __threadfence();                                  // acquire
    }
    __syncthreads();
}

__device__ __forceinline__ void issue_stage(uint32_t sb, int s, int it,
                                            const __half2* A1, const __half2* A2,
                                            const __half2* W1, const __half2* W2,
                                            int m0, int j0, int tid) {
    const __half2* Ap = (it < 16) ? A1 : A2;
    const __half2* Wp = (it < 16) ? W1 : W2;
    const int kk = (it & 15) << 4;
    const uint32_t as = sb + s * STAGE_B;
    const uint32_t ws = as + OFF_W;
    {   // A: 64 rows x 4 chunks, 1/thread
        int row = tid >> 2, u = tid & 3;
        CP_ASYNC16(as + (row << 6) + (u << 4),
                   Ap + (size_t)(m0 + row) * 256 + kk + u * 4);
    }
#pragma unroll
    for (int t2 = 0; t2 < 2; t2++) {    // W: 128 rows x 4 chunks, 2/thread
        int idx = tid + t2 * 256;
        int r = idx >> 2, u = idx & 3;
        int grow = (r & 3) * 512 + j0 + (r >> 2);
        CP_ASYNC16(ws + (r << 6) + (u << 4),
                   Wp + (size_t)grow * 256 + kk + u * 4);
    }
}

__global__ __launch_bounds__(256, 2) void lstm_persistent(
    const float* __restrict__ b_ih, const float* __restrict__ b_hh,
    const float* __restrict__ Wih32, const float* __restrict__ Whh32,
    float* __restrict__ out)
{
    extern __shared__ char smem[];
    const int cta = blockIdx.x;
    const int tid = threadIdx.x;

    // ---------------- converter CTAs ----------------
    if (cta >= NJOB) {
        const int w = cta - NJOB;
        for (int p = 0; p <= NSTEPS; p++) {
            if (p < NSTEPS - 1) {   // convert step p+1 (steps 1..29)
                int s = p + 1;
                const float* cIh = Wih32 + (size_t)(s * 2) * WSZF;
                const float* cHh = Whh32 + (size_t)(s * 2) * WSZF;
                __half2* dIh = g_w16ih + (size_t)(s * 2) * WPL2;
                __half2* dHh = g_w16hh + (size_t)(s * 2) * WPL2;
                for (int c = w * 256 + tid; c < 2 * CHUNKS_PER_TENSOR; c += NCONV * 256) {
                    if (c < CHUNKS_PER_TENSOR) convert_chunk(cIh, dIh, c);
                    else                       convert_chunk(cHh, dHh, c - CHUNKS_PER_TENSOR);
                }
            }
            if (p < NSTEPS) grid_barrier();
        }
        return;
    }

    // ---------------- job CTAs: fixed (layer, tile) for all steps ----------------
    const uint32_t sb = smem_u32(smem);
    const int layer = (cta < 128) ? 0 : 1;
    const int tile = cta & 127;
    const int m0 = (tile >> 4) * 64;
    const int j0 = (tile & 15) * 32;

    const int lane = tid & 31, wid = tid >> 5;
    const int wm = wid & 1;          // 2 m-groups x 32 rows
    const int wn = wid >> 1;         // 4 n-groups x 8 jj
    const int r4 = lane >> 2, u = lane & 3;
    const bool evn = !(u & 1);

    float* smc = (float*)(smem + SMC_OFF);   // c tile, resident across all phases
    float* smb = (float*)(smem + BIAS_OFF);
    float* smh = (float*)smem;               // overlays stage region in epilogue

    for (int i = tid; i < 64 * CPAD; i += 256) smc[i] = 0.f;
    __syncthreads();

    const int aoff = ((wm * 32 + r4) << 6) + (u << 4);
    const int boff = ((wn * 32 + r4) << 6) + (u << 4) + OFF_W;

    for (int p = 0; p <= NSTEPS; p++) {
        const bool active = (layer == 0) ? (p < NSTEPS) : (p >= 1);
        if (active) {
            const int t = (layer == 0) ? p : p - 1;
            const int wp = t & 1, rp = wp ^ 1;
            const __half2 *A1, *A2;
            if (layer == 0) {
                int xt = (t < NSTEPS - 1) ? t : NSTEPS - 2;  // source bug: step 29 reuses x[28]
                A1 = g_x16 + (size_t)xt * BH2;
                A2 = g_h16 + (size_t)(rp * 2 + 0) * BH2;
            } else {
                A1 = g_h16 + (size_t)(wp * 2 + 0) * BH2;
                A2 = g_h16 + (size_t)(rp * 2 + 1) * BH2;
            }
            const int widx = t * 2 + layer;
            const __half2* W1 = g_w16ih + (size_t)widx * WPL2;
            const __half2* W2 = g_w16hh + (size_t)widx * WPL2;
            __half2* h16o = g_h16 + (size_t)(wp * 2 + layer) * BH2;
            float* y   = (layer == 1) ? out + (size_t)t * BH : nullptr;
            float* h32 = (t == NSTEPS - 1) ? out + (size_t)(NSTEPS + layer) * BH : nullptr;

            if (tid < 128) {   // guard load-bearing: smb is 128 floats
                int g = tid >> 5, jj = tid & 31;
                smb[tid] = b_ih[(size_t)widx * GDIM + g * 512 + j0 + jj]
                         + b_hh[(size_t)widx * GDIM + g * 512 + j0 + jj];
            }

            float acc[2][4][4];
#pragma unroll
            for (int mt = 0; mt < 2; mt++)
#pragma unroll
                for (int nt = 0; nt < 4; nt++)
#pragma unroll
                    for (int e = 0; e < 4; e++) acc[mt][nt][e] = 0.f;

            issue_stage(sb, 0, 0, A1, A2, W1, W2, m0, j0, tid);
            issue_stage(sb, 1, 1, A1, A2, W1, W2, m0, j0, tid); CP_COMMIT();
            issue_stage(sb, 2, 2, A1, A2, W1, W2, m0, j0, tid);
            issue_stage(sb, 3, 3, A1, A2, W1, W2, m0, j0, tid); CP_COMMIT();

            int s = 0;
            for (int itp = 0; itp < NKB; itp += 2) {
                CP_WAIT1();
                __syncthreads();
                if (itp + 4 < NKB) {
                    int s4 = s + 4; if (s4 >= NSTAGE) s4 -= NSTAGE;
                    int s5 = s4 + 1; if (s5 >= NSTAGE) s5 -= NSTAGE;
                    issue_stage(sb, s4, itp + 4, A1, A2, W1, W2, m0, j0, tid);
                    issue_stage(sb, s5, itp + 5, A1, A2, W1, W2, m0, j0, tid);
                }
                CP_COMMIT();

#pragma unroll
                for (int h = 0; h < 2; h++) {
                    const char* st = smem + (s + h) * STAGE_B;
                    uint4 a0lo = *(const uint4*)(st + aoff);
                    uint4 a0hi = *(const uint4*)(st + aoff + 512);
                    uint4 a1lo = *(const uint4*)(st + aoff + 1024);
                    uint4 a1hi = *(const uint4*)(st + aoff + 1536);
#pragma unroll
                    for (int nt = 0; nt < 4; nt++) {
                        uint4 bb = *(const uint4*)(st + boff + (nt << 9));
                        mma_f16(acc[0][nt], a0lo.x, a0hi.x, a0lo.y, a0hi.y, bb.x, bb.y);
                        mma_f16(acc[0][nt], a0lo.z, a0hi.z, a0lo.w, a0hi.w, bb.z, bb.w);
                        mma_f16(acc[1][nt], a1lo.x, a1hi.x, a1lo.y, a1hi.y, bb.x, bb.y);
                        mma_f16(acc[1][nt], a1lo.z, a1hi.z, a1lo.w, a1hi.w, bb.z, bb.w);
                    }
                }
                s += 2; if (s == NSTAGE) s = 0;
            }

            // fused LSTM cell epilogue (c resident in smem)
            __syncthreads();
#pragma unroll
            for (int mt = 0; mt < 2; mt++) {
                const int row = wm * 32 + mt * 16 + r4 + (evn ? 0 : 8);
#pragma unroll
                for (int nt = 0; nt < 4; nt++) {
                    float x0 = __shfl_xor_sync(0xFFFFFFFFu, acc[mt][nt][0], 1);
                    float x1 = __shfl_xor_sync(0xFFFFFFFFu, acc[mt][nt][1], 1);
                    float x2 = __shfl_xor_sync(0xFFFFFFFFu, acc[mt][nt][2], 1);
                    float x3 = __shfl_xor_sync(0xFFFFFFFFu, acc[mt][nt][3], 1);
                    int jj = wn * 8 + nt * 2 + (u >> 1);
                    float vi = (evn ? acc[mt][nt][0] : x2) + smb[jj];
                    float vf = (evn ? acc[mt][nt][1] : x3) + smb[32 + jj];
                    float vg = (evn ? x0 : acc[mt][nt][2]) + smb[64 + jj];
                    float vo = (evn ? x1 : acc[mt][nt][3]) + smb[96 + jj];
                    float ii = fast_sigmoid(vi);
                    float ff = fast_sigmoid(vf);
                    float gg = fast_tanh(vg);
                    float oo = fast_sigmoid(vo);
                    float cn = ff * smc[row * CPAD + jj] + ii * gg;
                    float hn = oo * fast_tanh(cn);
                    smc[row * CPAD + jj] = cn;
                    smh[row * CPAD + jj] = hn;
                }
            }
            __syncthreads();

            for (int i = tid; i < 64 * 32; i += 256) {
                int r = i >> 5, jj = i & 31;
                size_t g = (size_t)(m0 + r) * HDIM + j0 + jj;
                float hv = smh[r * CPAD + jj];
                if (y)   y[g]   = hv;
                if (h32) h32[g] = hv;
            }
            for (int i = tid; i < 64 * 16; i += 256) {
                int r = i >> 4, q = i & 15;
                int pq = (q & 3) * 4 + (q >> 2);
                __half2 hv = __floats2half2_rn(smh[r * CPAD + 2 * q], smh[r * CPAD + 2 * q + 1]);
                h16o[(size_t)(m0 + r) * 256 + (j0 >> 1) + pq] = hv;
            }
        }
        if (p < NSTEPS) grid_barrier();
    }

    // final c -> output tail (layer0 then layer1)
    float* cdst = out + (size_t)(NSTEPS + 2 + layer) * BH;
    for (int i = tid; i < 64 * 32; i += 256) {
        int r = i >> 5, jj = i & 31;
        cdst[(size_t)(m0 + r) * HDIM + j0 + jj] = smc[r * CPAD + jj];
    }
}

// upfront conversions
__global__ __launch_bounds__(256) void conv_chunks(const float* __restrict__ src,
                                                   __half2* __restrict__ dst, int nChunks) {
    int c = blockIdx.x * 256 + threadIdx.x;
    if (c < nChunks) convert_chunk(src, dst, c);
}

__global__ void zero_state() {
    int i = blockIdx.x * 256 + threadIdx.x;
    if (i < 2 * BH2) g_h16[2 * BH2 + i] = __floats2half2_rn(0.f, 0.f);  // parity-1 planes
}

// ---------------- host ----------------
extern "C" void kernel_launch(void* const* d_in, const int* in_sizes, int n_in,
                              void* d_out, int out_size)
{
    const float* x    = (const float*)d_in[0];
    const float* W_ih = (const float*)d_in[1];
    const float* W_hh = (const float*)d_in[2];
    const float* b_ih = (const float*)d_in[3];
    const float* b_hh = (const float*)d_in[4];
    float* out = (float*)d_out;

    __half2 *w16ih, *w16hh, *x16;
    cudaGetSymbolAddress((void**)&w16ih, g_w16ih);
    cudaGetSymbolAddress((void**)&w16hh, g_w16hh);
    cudaGetSymbolAddress((void**)&x16,   g_x16);

    cudaFuncSetAttribute(lstm_persistent, cudaFuncAttributeMaxDynamicSharedMemorySize, SMEM_BYTES);

    // upfront: x, step-0 weights, zero h parity-1 planes
    conv_chunks<<<(NSTEPS * 512 * 16 + 255) / 256, 256>>>(x, x16, NSTEPS * 512 * 16);
    conv_chunks<<<(CHUNKS_PER_TENSOR + 255) / 256, 256>>>(W_ih, w16ih, CHUNKS_PER_TENSOR);
    conv_chunks<<<(CHUNKS_PER_TENSOR + 255) / 256, 256>>>(W_hh, w16hh, CHUNKS_PER_TENSOR);
    zero_state<<<(2 * BH2 + 255) / 256, 256>>>();

    lstm_persistent<<<NCTAS, 256, SMEM_BYTES>>>(b_ih, b_hh, W_ih, W_hh, out);
}